// round 6
// baseline (speedup 1.0000x reference)
#include <cuda_runtime.h>

#define DEPTH   8
#define NCLASS  10
#define NT      128
#define NREG    16    // float2 elements per thread; NT*NREG = 2048 = DIM/2

typedef unsigned long long u64;

// GF(2)-linear element swizzle: conflict-free u64 LDS/STS (per half-warp
// rank-4 verified) for store-B, gather(Emap), store-A, load-B patterns.
__device__ __host__ constexpr int Sz(int a) {
    return a ^ ((a >> 4) & 15) ^ (((a >> 9) & 1) << 3);
}
// CNOT-layer composite map in element space: old_e = Emap(new_e).
__device__ __host__ constexpr int Emap(int e) {
    return e ^ (e >> 1) ^ ((e >> 2) & 0x2AA);
}
__device__ __host__ constexpr int CB(int r)   { return (r << 5) ^ ((r & 7) << 1); } // Sz(r<<5)
__device__ __host__ constexpr int CG(int r)   { return Emap(r); }  // == Sz(Emap(r)) for r<16
__device__ __host__ constexpr bool SWP(int r) { return ((r ^ (r >> 1)) & 1) != 0; }

#define PACK2(d,x,y)   asm("mov.b64 %0,{%1,%2};" : "=l"(d) : "f"(x),"f"(y))
#define UNPACK2(x,y,d) asm("mov.b64 {%0,%1},%2;" : "=f"(x),"=f"(y) : "l"(d))
#define MUL2(d,a,b)    asm("mul.rn.f32x2 %0,%1,%2;" : "=l"(d) : "l"(a),"l"(b))
#define FMA2(d,a,b,c)  asm("fma.rn.f32x2 %0,%1,%2,%3;" : "=l"(d) : "l"(a),"l"(b),"l"(c))

// Packed lifting RY butterfly on 16 u64 regs along register-bit mask m.
__device__ __forceinline__ void lift16(u64* P, int m, u64 NP2, u64 S2) {
#pragma unroll
    for (int k = 0; k < NREG; k++)
        if (!(k & m)) {
            u64 U, V;
            FMA2(U, NP2, P[k | m], P[k]);      // u  = a0 - p*a1
            FMA2(V, S2,  U,        P[k | m]);  // a1'= a1 + s*u
            FMA2(P[k], NP2, V, U);             // a0'= u - p*a1'
            P[k | m] = V;
        }
}

// RY butterfly on a warp-lane bit via shfl_xor (standard form).
__device__ __forceinline__ void shflbf(u64* P, int lm, float c, float s, int t) {
    const float se = (t & lm) ? s : -s;
    u64 C2, SE2;
    PACK2(C2, c, c);
    PACK2(SE2, se, se);
#pragma unroll
    for (int r = 0; r < NREG; r++) {
        u64 part = __shfl_xor_sync(0xffffffffu, P[r], lm);
        u64 tm;
        MUL2(tm, SE2, part);
        FMA2(P[r], C2, P[r], tm);
    }
}

__global__ __launch_bounds__(NT, 6) void vqc_kernel(const float* __restrict__ X,
                                                    const float* __restrict__ W,
                                                    float* __restrict__ out) {
    __shared__ u64 smP[2048], smQ[2048];             // double-buffered statevector
    __shared__ u64 SS2[DEPTH * 12], PP2[DEPTH * 12]; // packed sin / -tan(phi/2)
    __shared__ float scC[DEPTH * 12], scS[DEPTH * 12], scP[DEPTH * 12];
    __shared__ float enc0[12], enc1[12];
    __shared__ float red[4][NCLASS];

    const int t = threadIdx.x;

    // ---- coefficient tables (96 entries, one per thread) ----
    if (t < DEPTH * 12) {
        float s_, c_;
        sincosf(0.5f * W[t], &s_, &c_);
        float np = -s_ / (1.0f + c_);
        u64 b2, c3;
        PACK2(b2, s_, s_);  PACK2(c3, np, np);
        SS2[t] = b2;  PP2[t] = c3;
        scC[t] = c_;  scS[t] = s_;  scP[t] = np;
    }
    if (t < 12) {
        float s_, c_;
        sincosf(0.5f * X[blockIdx.x * 12 + t], &s_, &c_);
        const float rr = 0.7071067811865476f;
        enc0[t] = (c_ - s_) * rr;
        enc1[t] = (c_ + s_) * rr;
    }
    __syncthreads();

    // ---- tilings ----
    // element bit ek = index bit k+1 = qubit 10-k; simd lane = qubit 11.
    // Tiling A (trip 1): e = (t<<4)|r. regs: q7(r3) q8(r2) q9(r1) q10(r0);
    //                    lane bit t0 = e4 = q6 (shfl).
    // Tiling B (trip 2 / resident): e10=t4, e9=t3, e8..e5=r3..r0,
    //                    e4=t6, e3=t5, e2=t2, e1=t1, e0=t0.
    //                    regs: q2(r3) q3(r2) q4(r1) q5(r0);
    //                    shfl: q0 = t4, q1 = t3.
    const int bA = (t << 4) ^ (t & 15) ^ (((t >> 5) & 1) << 3);   // Sz(t<<4)
    const int bG = Sz(Emap(t << 4));
    const int eB = (((t >> 4) & 1) << 10) | (((t >> 3) & 1) << 9) |
                   (((t >> 6) & 1) << 4)  | (((t >> 5) & 1) << 3) |
                   (t & 7);
    const int bB = Sz(eB);

    // ---- init: product state (H + encoding RY) in tiling B registers ----
    float base = ((t >> 6) & 1) ? enc1[6]  : enc0[6];
    base *= ((t >> 5) & 1)      ? enc1[7]  : enc0[7];
    base *= ((t >> 4) & 1)      ? enc1[0]  : enc0[0];
    base *= ((t >> 3) & 1)      ? enc1[1]  : enc0[1];
    base *= ((t >> 2) & 1)      ? enc1[8]  : enc0[8];
    base *= ((t >> 1) & 1)      ? enc1[9]  : enc0[9];
    base *= (t & 1)             ? enc1[10] : enc0[10];
    const float bx = base * enc0[11], by = base * enc1[11];

    u64 P[NREG];
#pragma unroll
    for (int r = 0; r < NREG; r++) {
        float rf = (r & 8) ? enc1[2] : enc0[2];
        rf *= (r & 4) ? enc1[3] : enc0[3];
        rf *= (r & 2) ? enc1[4] : enc0[4];
        rf *= (r & 1) ? enc1[5] : enc0[5];
        float x = rf * bx, y = rf * by;
        PACK2(P[r], x, y);
    }

#pragma unroll 1
    for (int k = 0; k < DEPTH; k++) {
        const int kc = k * 12;

        // ---- trip 1: store B -> gather (CNOT perm) + q11 -> q7..q10 -> shfl q6
#pragma unroll
        for (int r = 0; r < NREG; r++)
            smP[bB ^ CB(r)] = P[r];
        __syncthreads();

        const float np11 = scP[kc + 11];
        const float s11  = scS[kc + 11];
#pragma unroll
        for (int r = 0; r < NREG; r++) {
            float2 L = ((const float2*)smP)[bG ^ CG(r)];
            float x = SWP(r) ? L.y : L.x;
            float y = SWP(r) ? L.x : L.y;
            float u = fmaf(np11, y, x);
            float v = fmaf(s11, u, y);
            float w = fmaf(np11, v, u);
            PACK2(P[r], w, v);
        }
        lift16(P, 8, PP2[kc + 7],  SS2[kc + 7]);
        lift16(P, 4, PP2[kc + 8],  SS2[kc + 8]);
        lift16(P, 2, PP2[kc + 9],  SS2[kc + 9]);
        lift16(P, 1, PP2[kc + 10], SS2[kc + 10]);
        shflbf(P, 1, scC[kc + 6], scS[kc + 6], t);   // q6 on lane bit 0

        // ---- trip 2: store A (other buffer) -> load B -> q2..q5 -> shfl q0,q1
#pragma unroll
        for (int r = 0; r < NREG; r++)
            smQ[bA ^ r] = P[r];
        __syncthreads();
#pragma unroll
        for (int r = 0; r < NREG; r++)
            P[r] = smQ[bB ^ CB(r)];

        lift16(P, 8, PP2[kc + 2], SS2[kc + 2]);
        lift16(P, 4, PP2[kc + 3], SS2[kc + 3]);
        lift16(P, 2, PP2[kc + 4], SS2[kc + 4]);
        lift16(P, 1, PP2[kc + 5], SS2[kc + 5]);
        shflbf(P, 16, scC[kc + 0], scS[kc + 0], t);  // q0 on lane bit 4
        shflbf(P, 8,  scC[kc + 1], scS[kc + 1], t);  // q1 on lane bit 3
    }

    // ---- measurement from registers (tiling B) ----
    float T = 0.0f, A2 = 0.0f, A3 = 0.0f, A4 = 0.0f, A5 = 0.0f;
#pragma unroll
    for (int r = 0; r < NREG; r++) {
        float x, y;
        UNPACK2(x, y, P[r]);
        float p2 = fmaf(y, y, x * x);
        T += p2;
        if (!(r & 8)) A2 += p2;
        if (!(r & 4)) A3 += p2;
        if (!(r & 2)) A4 += p2;
        if (!(r & 1)) A5 += p2;
    }
    float loc[NCLASS];
    loc[0] = ((t >> 4) & 1) ? -T : T;   // q0 = t4
    loc[1] = ((t >> 3) & 1) ? -T : T;   // q1 = t3
    loc[2] = 2.0f * A2 - T;             // q2 = r3
    loc[3] = 2.0f * A3 - T;             // q3 = r2
    loc[4] = 2.0f * A4 - T;             // q4 = r1
    loc[5] = 2.0f * A5 - T;             // q5 = r0
    loc[6] = ((t >> 6) & 1) ? -T : T;   // q6 = t6
    loc[7] = ((t >> 5) & 1) ? -T : T;   // q7 = t5
    loc[8] = ((t >> 2) & 1) ? -T : T;   // q8 = t2
    loc[9] = ((t >> 1) & 1) ? -T : T;   // q9 = t1

#pragma unroll
    for (int p = 0; p < NCLASS; p++) {
        float v = loc[p];
#pragma unroll
        for (int o = 16; o > 0; o >>= 1)
            v += __shfl_xor_sync(0xffffffffu, v, o);
        if ((t & 31) == 0) red[t >> 5][p] = v;
    }
    __syncthreads();
    if (t < NCLASS)
        out[blockIdx.x * NCLASS + t] =
            (red[0][t] + red[1][t]) + (red[2][t] + red[3][t]);
}

extern "C" void kernel_launch(void* const* d_in, const int* in_sizes, int n_in,
                              void* d_out, int out_size) {
    const float* X = (const float*)d_in[0];   // [4096, 12] fp32
    const float* W = (const float*)d_in[1];   // [8, 12]    fp32
    float* out = (float*)d_out;               // [4096, 10] fp32
    const int batch = in_sizes[0] / 12;
    vqc_kernel<<<batch, NT>>>(X, W, out);
}

// round 7
// speedup vs baseline: 1.1217x; 1.1217x over previous
#include <cuda_runtime.h>

#define DEPTH   8
#define NCLASS  10
#define NT      64
#define NREG    32    // float2 elements per thread; NT*NREG = 2048 = DIM/2

typedef unsigned long long u64;

// GF(2)-linear element swizzle (conflict-free u64 LDS/STS for all patterns).
__device__ __host__ constexpr int Sz(int e) {
    return e ^ ((e >> 5) & 15) ^ (((e >> 10) & 1) << 3);
}
// CNOT-layer composite map in element space: old_e = Emap(new_e).
__device__ __host__ constexpr int Emap(int e) {
    return e ^ (e >> 1) ^ ((e >> 2) & 0x2AA);
}
__device__ __host__ constexpr int CBr(int r)  { return (r << 5) ^ (r & 15); } // Sz(r<<5)
__device__ __host__ constexpr int CGr(int r)  { return Emap(r); }             // Sz(Emap(r)), r<32
__device__ __host__ constexpr bool SWP(int r) { return ((r ^ (r >> 1)) & 1) != 0; }

#define PACK2(d,x,y)   asm("mov.b64 %0,{%1,%2};" : "=l"(d) : "f"(x),"f"(y))
#define UNPACK2(x,y,d) asm("mov.b64 {%0,%1},%2;" : "=f"(x),"=f"(y) : "l"(d))
#define MUL2(d,a,b)    asm("mul.rn.f32x2 %0,%1,%2;" : "=l"(d) : "l"(a),"l"(b))
#define FMA2(d,a,b,c)  asm("fma.rn.f32x2 %0,%1,%2,%3;" : "=l"(d) : "l"(a),"l"(b),"l"(c))

// Packed lifting RY butterfly on 32 u64 regs along register-bit mask m.
// NP2 = (-tan(phi/2))x2, S2 = (sin phi)x2.  3 FMA2 per pair.
__device__ __forceinline__ void lift32(u64* P, int m, u64 NP2, u64 S2) {
#pragma unroll
    for (int k = 0; k < NREG; k++)
        if (!(k & m)) {
            u64 U, V;
            FMA2(U, NP2, P[k | m], P[k]);      // u  = a0 - p*a1
            FMA2(V, S2,  U,        P[k | m]);  // a1'= a1 + s*u
            FMA2(P[k], NP2, V, U);             // a0'= u - p*a1'
            P[k | m] = V;
        }
}

__global__ __launch_bounds__(NT, 6) void vqc_kernel(const float* __restrict__ X,
                                                    const float* __restrict__ W,
                                                    float* __restrict__ out) {
    __shared__ u64 smP[2048];                         // store-B / gather buffer
    __shared__ u64 smQ[2048];                         // store-A / load-B buffer
    __shared__ u64 SS2[DEPTH * 12], PP2[DEPTH * 12];  // packed sin / -tan(phi/2)
    __shared__ float c0s[DEPTH], s0s[DEPTH];          // scalar coeffs, qubit 0
    __shared__ float np11s[DEPTH], s11s[DEPTH];       // scalar coeffs, qubit 11
    __shared__ float enc0[12], enc1[12];
    __shared__ float red[2][NCLASS];

    const int t = threadIdx.x;

    // ---- coefficient tables ----
    for (int i = t; i < DEPTH * 12; i += NT) {
        float s_, c_;
        sincosf(0.5f * W[i], &s_, &c_);
        float np = -s_ / (1.0f + c_);
        u64 b2, c3;
        PACK2(b2, s_, s_);  PACK2(c3, np, np);
        SS2[i] = b2;  PP2[i] = c3;
        const int q = i % 12, k = i / 12;
        if (q == 0)  { c0s[k] = c_;  s0s[k] = s_; }
        if (q == 11) { np11s[k] = np; s11s[k] = s_; }
    }
    if (t < 12) {
        float s_, c_;
        sincosf(0.5f * X[blockIdx.x * 12 + t], &s_, &c_);
        const float rr = 0.7071067811865476f;
        enc0[t] = (c_ - s_) * rr;
        enc1[t] = (c_ + s_) * rr;
    }
    __syncthreads();

    // ---- per-thread address bases (all maps GF(2)-linear) ----
    // Tiling A: e = (t<<5)|r   (regs = e4..0 -> qubits 6..10)
    // Tiling B: e = (t0<<10)|(r<<5)|((t>>1)&31)  (regs = e9..5 -> qubits 1..5)
    const int bA = (t << 5) ^ (t & 15) ^ (((t >> 5) & 1) << 3);
    const int bB = (((t & 1) << 10) | ((t >> 1) & 31)) ^ ((t & 1) << 3);
    int em = t << 5;
    em = em ^ (em >> 1) ^ ((em >> 2) & 0x2AA);
    const int bG = Sz(em);

    // ---- init: product state (H + encoding RY) in tiling B registers ----
    // thread bits: q0<-t0, q6<-t5, q7<-t4, q8<-t3, q9<-t2, q10<-t1
    float base = (t & 1)        ? enc1[0]  : enc0[0];
    base *= ((t >> 5) & 1)      ? enc1[6]  : enc0[6];
    base *= ((t >> 4) & 1)      ? enc1[7]  : enc0[7];
    base *= ((t >> 3) & 1)      ? enc1[8]  : enc0[8];
    base *= ((t >> 2) & 1)      ? enc1[9]  : enc0[9];
    base *= ((t >> 1) & 1)      ? enc1[10] : enc0[10];
    const float bx = base * enc0[11], by = base * enc1[11];

    u64 P[NREG];
#pragma unroll
    for (int r = 0; r < NREG; r++) {
        // reg bits: q1<-r4, q2<-r3, q3<-r2, q4<-r1, q5<-r0
        float rf = (r & 16) ? enc1[1] : enc0[1];
        rf *= (r & 8) ? enc1[2] : enc0[2];
        rf *= (r & 4) ? enc1[3] : enc0[3];
        rf *= (r & 2) ? enc1[4] : enc0[4];
        rf *= (r & 1) ? enc1[5] : enc0[5];
        float x = rf * bx, y = rf * by;
        PACK2(P[r], x, y);
    }

#pragma unroll 1
    for (int k = 0; k < DEPTH; k++) {
        const int kc = k * 12;

        // ---- trip 1: store B(smP) -> gather (CNOT perm) + q11 -> q6..q10 ----
        // Previous layer's gather reads of smP completed before the previous
        // post-store-A barrier; this store-B comes after it -> safe.
#pragma unroll
        for (int r = 0; r < NREG; r++)
            smP[bB ^ CBr(r)] = P[r];
        __syncthreads();                       // store-B visible before gather

        const float np11 = np11s[k];
        const float s11  = s11s[k];
#pragma unroll
        for (int r = 0; r < NREG; r++) {
            float2 L = ((const float2*)smP)[bG ^ CGr(r)];
            float x = SWP(r) ? L.y : L.x;
            float y = SWP(r) ? L.x : L.y;
            // SIMD qubit 11 (lifting, scalar)
            float u = fmaf(np11, y, x);
            float v = fmaf(s11, u, y);
            float w = fmaf(np11, v, u);
            PACK2(P[r], w, v);
        }
        lift32(P, 16, PP2[kc + 6],  SS2[kc + 6]);   // q6  <-> r4
        lift32(P, 8,  PP2[kc + 7],  SS2[kc + 7]);   // q7
        lift32(P, 4,  PP2[kc + 8],  SS2[kc + 8]);   // q8
        lift32(P, 2,  PP2[kc + 9],  SS2[kc + 9]);   // q9
        lift32(P, 1,  PP2[kc + 10], SS2[kc + 10]);  // q10

        // ---- trip 2: store A(smQ) -> load B(smQ) -> q1..q5 + shfl q0 ----
#pragma unroll
        for (int r = 0; r < NREG; r++)
            smQ[bA ^ r] = P[r];
        __syncthreads();                       // store-A visible before load-B
#pragma unroll
        for (int r = 0; r < NREG; r++)
            P[r] = smQ[bB ^ CBr(r)];

        lift32(P, 16, PP2[kc + 1], SS2[kc + 1]);    // q1 <-> r4
        lift32(P, 8,  PP2[kc + 2], SS2[kc + 2]);
        lift32(P, 4,  PP2[kc + 3], SS2[kc + 3]);
        lift32(P, 2,  PP2[kc + 4], SS2[kc + 4]);
        lift32(P, 1,  PP2[kc + 5], SS2[kc + 5]);

        // qubit 0 on lane bit t0: butterfly via shfl_xor
        {
            const float c0 = c0s[k];
            const float s0 = s0s[k];
            const float se = (t & 1) ? s0 : -s0;
            u64 C2x, SE2;
            PACK2(C2x, c0, c0);
            PACK2(SE2, se, se);
#pragma unroll
            for (int r = 0; r < NREG; r++) {
                u64 part = __shfl_xor_sync(0xffffffffu, P[r], 1);
                u64 tm;
                MUL2(tm, SE2, part);
                FMA2(P[r], C2x, P[r], tm);
            }
        }
        // NOTE: no loop-end barrier. Next layer's store-B (smP) is ordered
        // against this layer's gather reads by the post-store-A barrier above;
        // load-B reads (smQ) are ordered against next layer's store-A by the
        // next layer's post-store-B barrier.
    }

    // ---- measurement from registers (tiling B) ----
    float T = 0.0f, A1 = 0.0f, A2 = 0.0f, A3 = 0.0f, A4 = 0.0f, A5 = 0.0f;
#pragma unroll
    for (int r = 0; r < NREG; r++) {
        float x, y;
        UNPACK2(x, y, P[r]);
        float p2 = fmaf(y, y, x * x);
        T += p2;
        if (!(r & 16)) A1 += p2;
        if (!(r & 8))  A2 += p2;
        if (!(r & 4))  A3 += p2;
        if (!(r & 2))  A4 += p2;
        if (!(r & 1))  A5 += p2;
    }
    float loc[NCLASS];
    loc[0] = (t & 1)        ? -T : T;
    loc[1] = 2.0f * A1 - T;
    loc[2] = 2.0f * A2 - T;
    loc[3] = 2.0f * A3 - T;
    loc[4] = 2.0f * A4 - T;
    loc[5] = 2.0f * A5 - T;
    loc[6] = ((t >> 5) & 1) ? -T : T;
    loc[7] = ((t >> 4) & 1) ? -T : T;
    loc[8] = ((t >> 3) & 1) ? -T : T;
    loc[9] = ((t >> 2) & 1) ? -T : T;

#pragma unroll
    for (int p = 0; p < NCLASS; p++) {
        float v = loc[p];
#pragma unroll
        for (int o = 16; o > 0; o >>= 1)
            v += __shfl_xor_sync(0xffffffffu, v, o);
        if ((t & 31) == 0) red[t >> 5][p] = v;
    }
    __syncthreads();
    if (t < NCLASS)
        out[blockIdx.x * NCLASS + t] = red[0][t] + red[1][t];
}

extern "C" void kernel_launch(void* const* d_in, const int* in_sizes, int n_in,
                              void* d_out, int out_size) {
    const float* X = (const float*)d_in[0];   // [4096, 12] fp32
    const float* W = (const float*)d_in[1];   // [8, 12]    fp32
    float* out = (float*)d_out;               // [4096, 10] fp32
    const int batch = in_sizes[0] / 12;
    vqc_kernel<<<batch, NT>>>(X, W, out);
}